// round 3
// baseline (speedup 1.0000x reference)
#include <cuda_runtime.h>
#include <cuda_bf16.h>

// out[b,k] = sum_{i,j} x[b,i] * W[k,i,j] * x[b,j]
// prep: Wp[t][k] = W[k,i,i] (i==j) or W[k,i,j]+W[k,j,i] (i<j), t = pair index (i<=j).
// main: 4 batch rows per thread; per pair, 4 broadcast LDS.128 of W feed
//       32 packed f32x2 FMAs (8 per row) -> 8 fma per LDS.

#define NPAIR 136
#define WP_ELEMS (NPAIR * 16)
#define R 4

__device__ float d_Wp[WP_ELEMS];

typedef unsigned long long ull;

__device__ __forceinline__ ull pack2(float lo, float hi) {
    ull r;
    asm("mov.b64 %0, {%1, %2};" : "=l"(r) : "f"(lo), "f"(hi));
    return r;
}

__device__ __forceinline__ ull ffma2(ull a, ull b, ull c) {
    ull r;
    asm("fma.rn.f32x2 %0, %1, %2, %3;" : "=l"(r) : "l"(a), "l"(b), "l"(c));
    return r;
}

__global__ void prep_kernel(const float* __restrict__ W) {
    int idx = blockIdx.x * blockDim.x + threadIdx.x;
    if (idx >= WP_ELEMS) return;
    int t = idx >> 4;
    int k = idx & 15;
    int i = 0, rem = t;
    while (rem >= 16 - i) { rem -= 16 - i; ++i; }
    int j = i + rem;
    float v = W[k * 256 + i * 16 + j];
    if (i != j) v += W[k * 256 + j * 16 + i];
    d_Wp[idx] = v;
}

__global__ void __launch_bounds__(256, 1)
bilinear_kernel(const float* __restrict__ x, float* __restrict__ out) {
    __shared__ __align__(16) float sW[WP_ELEMS];
    for (int idx = threadIdx.x; idx < WP_ELEMS; idx += 256)
        sW[idx] = d_Wp[idx];
    __syncthreads();

    // R rows per thread, all coalesced: b_r = blockBase + r*256 + tid
    unsigned int base = blockIdx.x * (256u * R) + threadIdx.x;

    float xs[R][16];
#pragma unroll
    for (int r = 0; r < R; ++r) {
        const float4* xr = (const float4*)(x + (size_t)(base + r * 256u) * 16);
#pragma unroll
        for (int q = 0; q < 4; ++q) {
            float4 v = xr[q];
            xs[r][q * 4 + 0] = v.x; xs[r][q * 4 + 1] = v.y;
            xs[r][q * 4 + 2] = v.z; xs[r][q * 4 + 3] = v.w;
        }
    }

    // acc[r][p] holds packed (out[2p], out[2p+1]) for row r
    ull acc[R][8];
#pragma unroll
    for (int r = 0; r < R; ++r)
#pragma unroll
        for (int p = 0; p < 8; ++p) acc[r][p] = 0ull;

    int t = 0;
#pragma unroll
    for (int i = 0; i < 16; ++i) {
#pragma unroll
        for (int j = i; j < 16; ++j) {
            const ulonglong2* wrow = (const ulonglong2*)(sW + t * 16);
            ulonglong2 w0 = wrow[0];
            ulonglong2 w1 = wrow[1];
            ulonglong2 w2 = wrow[2];
            ulonglong2 w3 = wrow[3];
            ull sp[R];
#pragma unroll
            for (int r = 0; r < R; ++r) {
                float s = xs[r][i] * xs[r][j];
                sp[r] = pack2(s, s);
            }
#pragma unroll
            for (int r = 0; r < R; ++r) {
                acc[r][0] = ffma2(w0.x, sp[r], acc[r][0]);
                acc[r][1] = ffma2(w0.y, sp[r], acc[r][1]);
                acc[r][2] = ffma2(w1.x, sp[r], acc[r][2]);
                acc[r][3] = ffma2(w1.y, sp[r], acc[r][3]);
                acc[r][4] = ffma2(w2.x, sp[r], acc[r][4]);
                acc[r][5] = ffma2(w2.y, sp[r], acc[r][5]);
                acc[r][6] = ffma2(w3.x, sp[r], acc[r][6]);
                acc[r][7] = ffma2(w3.y, sp[r], acc[r][7]);
            }
            ++t;
        }
    }

#pragma unroll
    for (int r = 0; r < R; ++r) {
        ulonglong2* o = (ulonglong2*)(out + (size_t)(base + r * 256u) * 16);
        o[0] = make_ulonglong2(acc[r][0], acc[r][1]);
        o[1] = make_ulonglong2(acc[r][2], acc[r][3]);
        o[2] = make_ulonglong2(acc[r][4], acc[r][5]);
        o[3] = make_ulonglong2(acc[r][6], acc[r][7]);
    }
}

extern "C" void kernel_launch(void* const* d_in, const int* in_sizes, int n_in,
                              void* d_out, int out_size) {
    const float* x = (const float*)d_in[0];
    const float* W = (const float*)d_in[1];
    if (n_in >= 2 && in_sizes[0] == 4096) {  // defensive input identification
        W = (const float*)d_in[0];
        x = (const float*)d_in[1];
    }
    float* out = (float*)d_out;

    prep_kernel<<<(WP_ELEMS + 255) / 256, 256>>>(W);

    const unsigned int B = 1048576u;
    bilinear_kernel<<<B / (256 * R), 256>>>(x, out);
}

// round 5
// speedup vs baseline: 1.2266x; 1.2266x over previous
#include <cuda_runtime.h>
#include <cuda_bf16.h>
#include <cstdint>

// out[b,k] = sum_{i,j} x[b,i] * W[k,i,j] * x[b,j]
// prep: Wp[t][k] = W[k,i,i] (i==j) or W[k,i,j]+W[k,j,i] (i<j), t = pair index (i<=j).
// main: 2 batch rows per thread. W comes from the CONSTANT bank (separate port,
//       zero smem-crossbar traffic); per pair 4x LDC.128 feed 16 packed f32x2 FMAs.

#define NPAIR 136
#define WP_ELEMS (NPAIR * 16)

__device__ float d_Wp[WP_ELEMS];                 // staging (written by prep kernel)
__constant__ ulonglong2 c_Wp[NPAIR * 4];         // same data, constant bank, 16B granules

typedef unsigned long long ull;

__device__ __forceinline__ ull pack2(float lo, float hi) {
    ull r;
    asm("mov.b64 %0, {%1, %2};" : "=l"(r) : "f"(lo), "f"(hi));
    return r;
}

__device__ __forceinline__ ull ffma2(ull a, ull b, ull c) {
    ull r;
    asm("fma.rn.f32x2 %0, %1, %2, %3;" : "=l"(r) : "l"(a), "l"(b), "l"(c));
    return r;
}

__global__ void prep_kernel(const float* __restrict__ W) {
    int idx = blockIdx.x * blockDim.x + threadIdx.x;
    if (idx >= WP_ELEMS) return;
    int t = idx >> 4;
    int k = idx & 15;
    int i = 0, rem = t;
    while (rem >= 16 - i) { rem -= 16 - i; ++i; }
    int j = i + rem;
    float v = W[k * 256 + i * 16 + j];
    if (i != j) v += W[k * 256 + j * 16 + i];
    d_Wp[idx] = v;
}

__global__ void __launch_bounds__(256, 3)
bilinear_kernel(const float* __restrict__ x, float* __restrict__ out) {
    // two rows per thread, both coalesced
    unsigned int b0 = blockIdx.x * 512u + threadIdx.x;
    unsigned int b1 = b0 + 256u;

    float x0[16], x1[16];
    {
        const float4* r0 = (const float4*)(x + (size_t)b0 * 16);
        const float4* r1 = (const float4*)(x + (size_t)b1 * 16);
#pragma unroll
        for (int q = 0; q < 4; ++q) {
            float4 v0 = r0[q];
            float4 v1 = r1[q];
            x0[q * 4 + 0] = v0.x; x0[q * 4 + 1] = v0.y;
            x0[q * 4 + 2] = v0.z; x0[q * 4 + 3] = v0.w;
            x1[q * 4 + 0] = v1.x; x1[q * 4 + 1] = v1.y;
            x1[q * 4 + 2] = v1.z; x1[q * 4 + 3] = v1.w;
        }
    }

    ull acc0[8], acc1[8];
#pragma unroll
    for (int p = 0; p < 8; ++p) { acc0[p] = 0ull; acc1[p] = 0ull; }

    int t = 0;
#pragma unroll
    for (int i = 0; i < 16; ++i) {
#pragma unroll
        for (int j = i; j < 16; ++j) {
            float s0 = x0[i] * x0[j];
            float s1 = x1[i] * x1[j];
            ull s0p = pack2(s0, s0);
            ull s1p = pack2(s1, s1);
            // 16 k-channels from the constant bank: 4x 128-bit loads (t is compile-time)
            ulonglong2 w0 = c_Wp[t * 4 + 0];
            ulonglong2 w1 = c_Wp[t * 4 + 1];
            ulonglong2 w2 = c_Wp[t * 4 + 2];
            ulonglong2 w3 = c_Wp[t * 4 + 3];
            acc0[0] = ffma2(w0.x, s0p, acc0[0]);
            acc0[1] = ffma2(w0.y, s0p, acc0[1]);
            acc0[2] = ffma2(w1.x, s0p, acc0[2]);
            acc0[3] = ffma2(w1.y, s0p, acc0[3]);
            acc0[4] = ffma2(w2.x, s0p, acc0[4]);
            acc0[5] = ffma2(w2.y, s0p, acc0[5]);
            acc0[6] = ffma2(w3.x, s0p, acc0[6]);
            acc0[7] = ffma2(w3.y, s0p, acc0[7]);
            acc1[0] = ffma2(w0.x, s1p, acc1[0]);
            acc1[1] = ffma2(w0.y, s1p, acc1[1]);
            acc1[2] = ffma2(w1.x, s1p, acc1[2]);
            acc1[3] = ffma2(w1.y, s1p, acc1[3]);
            acc1[4] = ffma2(w2.x, s1p, acc1[4]);
            acc1[5] = ffma2(w2.y, s1p, acc1[5]);
            acc1[6] = ffma2(w3.x, s1p, acc1[6]);
            acc1[7] = ffma2(w3.y, s1p, acc1[7]);
            ++t;
        }
    }

    ulonglong2* o0 = (ulonglong2*)(out + (size_t)b0 * 16);
    ulonglong2* o1 = (ulonglong2*)(out + (size_t)b1 * 16);
    o0[0] = make_ulonglong2(acc0[0], acc0[1]);
    o0[1] = make_ulonglong2(acc0[2], acc0[3]);
    o0[2] = make_ulonglong2(acc0[4], acc0[5]);
    o0[3] = make_ulonglong2(acc0[6], acc0[7]);
    o1[0] = make_ulonglong2(acc1[0], acc1[1]);
    o1[1] = make_ulonglong2(acc1[2], acc1[3]);
    o1[2] = make_ulonglong2(acc1[4], acc1[5]);
    o1[3] = make_ulonglong2(acc1[6], acc1[7]);
}

extern "C" void kernel_launch(void* const* d_in, const int* in_sizes, int n_in,
                              void* d_out, int out_size) {
    const float* x = (const float*)d_in[0];
    const float* W = (const float*)d_in[1];
    if (n_in >= 2 && in_sizes[0] == 4096) {  // defensive input identification
        W = (const float*)d_in[0];
        x = (const float*)d_in[1];
    }
    float* out = (float*)d_out;

    // 1) symmetrize W into staging global
    prep_kernel<<<(WP_ELEMS + 255) / 256, 256>>>(W);

    // 2) copy staging -> constant bank (async D2D memcpy, graph-capturable)
    static void* wp_addr = nullptr;
    if (!wp_addr) cudaGetSymbolAddress(&wp_addr, d_Wp);
    cudaMemcpyToSymbolAsync(c_Wp, wp_addr, WP_ELEMS * sizeof(float), 0,
                            cudaMemcpyDeviceToDevice, 0);

    // 3) main kernel
    const unsigned int B = 1048576u;
    bilinear_kernel<<<B / 512, 256>>>(x, out);
}

// round 6
// speedup vs baseline: 1.8772x; 1.5304x over previous
#include <cuda_runtime.h>
#include <cuda_bf16.h>
#include <cstdint>

// out[b,k] = sum_{i,j} x[b,i] W[k,i,j] x[b,j]
// Diagonal pair enumeration: k-step kk (0..8), slot c (0..15) -> pair (i=c, j=(c+kk)&15).
// Wd[kk][c][n] = W[n,c,c] (kk=0), W[n,c,j]+W[n,j,c] (kk=1..7; kk=8 & c<8), 0 (kk=8, c>=8).
// GEMM per warp-tile: D[16 rows x 16 ch] += A[16 x 144] * B[144 x 16] via
// mma.sync.m16n8k16 bf16 (legacy HMMA, valid on plain sm_103), with hi/lo split:
// D = Ahi*Bhi + Alo*Bhi + Ahi*Blo  (lo*lo dropped).

#define NKST 9
#define ITER 4
#define WARPS 8
#define ROWS_PER_BLOCK (WARPS * ITER * 16)  // 512

// B fragment tables: [kk][nt][lane] -> uint2 {b0pack, b1pack}
__device__ uint2 g_BH[NKST * 2 * 32];
__device__ uint2 g_BL[NKST * 2 * 32];

__device__ __forceinline__ float wd_val(const float* W, int d, int i, int n) {
    int j = (i + d) & 15;
    float v = W[n * 256 + i * 16 + j];
    if (d == 0) return v;
    if (d == 8 && i >= 8) return 0.0f;
    return v + W[n * 256 + j * 16 + i];
}

__device__ __forceinline__ uint32_t pack_bf16_pair(float lo_elem, float hi_elem) {
    __nv_bfloat16 l = __float2bfloat16(lo_elem);
    __nv_bfloat16 h = __float2bfloat16(hi_elem);
    return (uint32_t)*(uint16_t*)&l | ((uint32_t)*(uint16_t*)&h << 16);
}

__global__ void prep_kernel(const float* __restrict__ W) {
    int id = blockIdx.x * blockDim.x + threadIdx.x;
    if (id >= NKST * 2 * 32) return;
    int lane = id & 31;
    int nt = (id >> 5) & 1;
    int kk = id >> 6;
    int gr = lane >> 2, tc = lane & 3;
    int n = nt * 8 + gr;

    float w[4];
    w[0] = wd_val(W, kk, tc * 2, n);
    w[1] = wd_val(W, kk, tc * 2 + 1, n);
    w[2] = wd_val(W, kk, tc * 2 + 8, n);
    w[3] = wd_val(W, kk, tc * 2 + 9, n);

    float hi[4], lo[4];
#pragma unroll
    for (int e = 0; e < 4; ++e) {
        __nv_bfloat16 h = __float2bfloat16(w[e]);
        hi[e] = __bfloat162float(h);
        lo[e] = w[e] - hi[e];
    }
    g_BH[id] = make_uint2(pack_bf16_pair(hi[0], hi[1]), pack_bf16_pair(hi[2], hi[3]));
    g_BL[id] = make_uint2(pack_bf16_pair(lo[0], lo[1]), pack_bf16_pair(lo[2], lo[3]));
}

// hi16 of two floats packed as bf16x2 (truncation): low half = a, high half = b
__device__ __forceinline__ uint32_t prmt_hi(float a, float b) {
    uint32_t r;
    asm("prmt.b32 %0, %1, %2, 0x7632;"
        : "=r"(r) : "r"(__float_as_uint(a)), "r"(__float_as_uint(b)));
    return r;
}
__device__ __forceinline__ float hipart(float a) {
    return __uint_as_float(__float_as_uint(a) & 0xFFFF0000u);
}

__device__ __forceinline__ void hmma(float& d0, float& d1, float& d2, float& d3,
                                     uint32_t a0, uint32_t a1, uint32_t a2, uint32_t a3,
                                     uint32_t b0, uint32_t b1) {
    asm volatile(
        "mma.sync.aligned.m16n8k16.row.col.f32.bf16.bf16.f32 "
        "{%0,%1,%2,%3}, {%4,%5,%6,%7}, {%8,%9}, {%0,%1,%2,%3};"
        : "+f"(d0), "+f"(d1), "+f"(d2), "+f"(d3)
        : "r"(a0), "r"(a1), "r"(a2), "r"(a3), "r"(b0), "r"(b1));
}

__global__ void __launch_bounds__(256, 2)
bilinear_hmma(const float* __restrict__ x, float* __restrict__ out) {
    __shared__ uint2 sBH[NKST * 2 * 32];
    __shared__ uint2 sBL[NKST * 2 * 32];
    __shared__ float sX[WARPS][16][16];

    int tid = threadIdx.x;
    int wid = tid >> 5, lane = tid & 31;
    int gr = lane >> 2, tc = lane & 3;
    int i0 = tc * 2;

    for (int i = tid; i < NKST * 2 * 32; i += 256) {
        sBH[i] = g_BH[i];
        sBL[i] = g_BL[i];
    }
    __syncthreads();

#pragma unroll 1
    for (int it = 0; it < ITER; ++it) {
        int tb = blockIdx.x * ROWS_PER_BLOCK + (wid * ITER + it) * 16;

        // stage this warp's 16 x-rows into smem (coalesced)
        {
            const float4* g = (const float4*)(x + (size_t)tb * 16);
            float4 v0 = g[lane];
            float4 v1 = g[lane + 32];
            *(float4*)&sX[wid][lane >> 2][(lane & 3) * 4] = v0;
            *(float4*)&sX[wid][(lane + 32) >> 2][(lane & 3) * 4] = v1;
        }
        __syncwarp();

        // rotated register copies: xr[m] = x_row[(i0+m)&15] -> all later indices compile-time
        float xr0[16], xr1[16];
#pragma unroll
        for (int m = 0; m < 16; m += 2) {
            int c = (i0 + m) & 15;
            float2 v0 = *(const float2*)&sX[wid][gr][c];
            float2 v1 = *(const float2*)&sX[wid][gr + 8][c];
            xr0[m] = v0.x; xr0[m + 1] = v0.y;
            xr1[m] = v1.x; xr1[m + 1] = v1.y;
        }

        float acc0[4] = {0.f, 0.f, 0.f, 0.f};
        float acc1[4] = {0.f, 0.f, 0.f, 0.f};

#pragma unroll
        for (int kk = 0; kk < NKST; ++kk) {
            // products for A-fragment slots (cols i0+{0,1,8,9} of this k-step)
            float p0 = xr0[0] * xr0[(0 + kk) & 15];
            float p1 = xr0[1] * xr0[(1 + kk) & 15];
            float p2 = xr0[8] * xr0[(8 + kk) & 15];
            float p3 = xr0[9] * xr0[(9 + kk) & 15];
            float q0 = xr1[0] * xr1[(0 + kk) & 15];
            float q1 = xr1[1] * xr1[(1 + kk) & 15];
            float q2 = xr1[8] * xr1[(8 + kk) & 15];
            float q3 = xr1[9] * xr1[(9 + kk) & 15];

            uint32_t a0h = prmt_hi(p0, p1);
            uint32_t a1h = prmt_hi(q0, q1);
            uint32_t a2h = prmt_hi(p2, p3);
            uint32_t a3h = prmt_hi(q2, q3);

            float p0l = p0 - hipart(p0), p1l = p1 - hipart(p1);
            float p2l = p2 - hipart(p2), p3l = p3 - hipart(p3);
            float q0l = q0 - hipart(q0), q1l = q1 - hipart(q1);
            float q2l = q2 - hipart(q2), q3l = q3 - hipart(q3);

            uint32_t a0l = prmt_hi(p0l, p1l);
            uint32_t a1l = prmt_hi(q0l, q1l);
            uint32_t a2l = prmt_hi(p2l, p3l);
            uint32_t a3l = prmt_hi(q2l, q3l);

            {
                uint2 bh = sBH[(kk * 2 + 0) * 32 + lane];
                uint2 bl = sBL[(kk * 2 + 0) * 32 + lane];
                hmma(acc0[0], acc0[1], acc0[2], acc0[3], a0h, a1h, a2h, a3h, bh.x, bh.y);
                hmma(acc0[0], acc0[1], acc0[2], acc0[3], a0l, a1l, a2l, a3l, bh.x, bh.y);
                hmma(acc0[0], acc0[1], acc0[2], acc0[3], a0h, a1h, a2h, a3h, bl.x, bl.y);
            }
            {
                uint2 bh = sBH[(kk * 2 + 1) * 32 + lane];
                uint2 bl = sBL[(kk * 2 + 1) * 32 + lane];
                hmma(acc1[0], acc1[1], acc1[2], acc1[3], a0h, a1h, a2h, a3h, bh.x, bh.y);
                hmma(acc1[0], acc1[1], acc1[2], acc1[3], a0l, a1l, a2l, a3l, bh.x, bh.y);
                hmma(acc1[0], acc1[1], acc1[2], acc1[3], a0h, a1h, a2h, a3h, bl.x, bl.y);
            }
        }

        // epilogue: D layout m16n8: d0=D[gr][tc*2], d1=D[gr][tc*2+1], d2=D[gr+8][...], d3
        {
            float* o0 = out + (size_t)(tb + gr) * 16;
            float* o1 = out + (size_t)(tb + gr + 8) * 16;
            *(float2*)(o0 + tc * 2)     = make_float2(acc0[0], acc0[1]);
            *(float2*)(o1 + tc * 2)     = make_float2(acc0[2], acc0[3]);
            *(float2*)(o0 + 8 + tc * 2) = make_float2(acc1[0], acc1[1]);
            *(float2*)(o1 + 8 + tc * 2) = make_float2(acc1[2], acc1[3]);
        }
        __syncwarp();  // protect sX before next iteration overwrites it
    }
}

extern "C" void kernel_launch(void* const* d_in, const int* in_sizes, int n_in,
                              void* d_out, int out_size) {
    const float* x = (const float*)d_in[0];
    const float* W = (const float*)d_in[1];
    if (n_in >= 2 && in_sizes[0] == 4096) {  // defensive input identification
        W = (const float*)d_in[0];
        x = (const float*)d_in[1];
    }
    float* out = (float*)d_out;

    prep_kernel<<<3, 256>>>(W);  // 576 table entries

    const unsigned int B = 1048576u;
    bilinear_hmma<<<B / ROWS_PER_BLOCK, 256>>>(x, out);
}